// round 15
// baseline (speedup 1.0000x reference)
#include <cuda_runtime.h>
#include <cuda_fp16.h>
#include <math.h>
#include <stdint.h>

#define BATCH 2
#define SEQ   2048
#define EMB   1024
#define HEADS 16
#define HDIM  64
#define FFDIM 4096
#define MROWS (BATCH * SEQ)   // 4096
#define QKVN  (3 * EMB)       // 3072

// ----------------------------------------------------------------------------
// Scratch (device globals — no runtime allocation allowed)
// ----------------------------------------------------------------------------
__device__ __half g_h   [MROWS * EMB];
__device__ __half g_qkv [MROWS * QKVN];
__device__ __half g_ctx [MROWS * EMB];
__device__ float  g_x1  [MROWS * EMB];
__device__ __half g_ff  [MROWS * FFDIM];
__device__ __half g_wqkv[EMB * QKVN];
__device__ __half g_wo  [EMB * EMB];
__device__ __half g_w1  [EMB * FFDIM];
__device__ __half g_w2  [FFDIM * EMB];

// ----------------------------------------------------------------------------
// Helpers
// ----------------------------------------------------------------------------
__device__ __forceinline__ uint32_t smem_u32(const void* p) {
    uint32_t a;
    asm("{ .reg .u64 t; cvta.to.shared.u64 t, %1; cvt.u32.u64 %0, t; }" : "=r"(a) : "l"(p));
    return a;
}
__device__ __forceinline__ void cp16(void* dst, const void* src) {
    asm volatile("cp.async.cg.shared.global [%0], [%1], 16;"
                 :: "r"(smem_u32(dst)), "l"(src) : "memory");
}
// gelu_tanh == x * sigmoid(2u), u = c*(x + 0.044715 x^3). Same function, cheap.
__device__ __forceinline__ float gelu_tanh(float x) {
    float u2 = 1.5957691216f * x * (1.0f + 0.044715f * x * x);   // = 2u
    return __fdividef(x, 1.0f + __expf(-u2));
}
__device__ __forceinline__ void ldsm_x4(uint32_t* r, uint32_t addr) {
    asm volatile("ldmatrix.sync.aligned.m8n8.x4.shared.b16 {%0,%1,%2,%3}, [%4];"
                 : "=r"(r[0]), "=r"(r[1]), "=r"(r[2]), "=r"(r[3]) : "r"(addr));
}
__device__ __forceinline__ void ldsm_x4t(uint32_t* r, uint32_t addr) {
    asm volatile("ldmatrix.sync.aligned.m8n8.x4.trans.shared.b16 {%0,%1,%2,%3}, [%4];"
                 : "=r"(r[0]), "=r"(r[1]), "=r"(r[2]), "=r"(r[3]) : "r"(addr));
}
__device__ __forceinline__ void mma16(float* c, const uint32_t* a, const uint32_t* b) {
    asm volatile(
        "mma.sync.aligned.m16n8k16.row.col.f32.f16.f16.f32 "
        "{%0,%1,%2,%3}, {%4,%5,%6,%7}, {%8,%9}, {%0,%1,%2,%3};"
        : "+f"(c[0]), "+f"(c[1]), "+f"(c[2]), "+f"(c[3])
        : "r"(a[0]), "r"(a[1]), "r"(a[2]), "r"(a[3]), "r"(b[0]), "r"(b[1]));
}

// ----------------------------------------------------------------------------
// LayerNorm: fp32 in, fp16 out
// ----------------------------------------------------------------------------
__inline__ __device__ float warp_sum(float v) {
    #pragma unroll
    for (int o = 16; o > 0; o >>= 1) v += __shfl_xor_sync(0xffffffffu, v, o);
    return v;
}
__global__ void ln_kernel(const float* __restrict__ x,
                          const float* __restrict__ scale,
                          const float* __restrict__ shift,
                          __half* __restrict__ out)
{
    __shared__ float ssum[8], ssq[8];
    int row = blockIdx.x;
    int t = threadIdx.x;
    const float4* xr = (const float4*)(x + (size_t)row * EMB);
    float4 v = xr[t];
    float s  = v.x + v.y + v.z + v.w;
    float sq = v.x * v.x + v.y * v.y + v.z * v.z + v.w * v.w;
    float ws  = warp_sum(s);
    float wsq = warp_sum(sq);
    int lane = t & 31, wid = t >> 5;
    if (lane == 0) { ssum[wid] = ws; ssq[wid] = wsq; }
    __syncthreads();
    float tot = 0.f, totsq = 0.f;
    #pragma unroll
    for (int i = 0; i < 8; i++) { tot += ssum[i]; totsq += ssq[i]; }
    float mean = tot * (1.0f / EMB);
    float var  = totsq * (1.0f / EMB) - mean * mean;
    float inv  = rsqrtf(var + 1e-5f);
    float4 sc = ((const float4*)scale)[t];
    float4 sh = ((const float4*)shift)[t];
    __half* op = out + (size_t)row * EMB + t * 4;
    *(half2*)op       = __floats2half2_rn(sc.x * (v.x - mean) * inv + sh.x,
                                          sc.y * (v.y - mean) * inv + sh.y);
    *(half2*)(op + 2) = __floats2half2_rn(sc.z * (v.z - mean) * inv + sh.z,
                                          sc.w * (v.w - mean) * inv + sh.w);
}

// ----------------------------------------------------------------------------
// Weight prep: fp32 -> fp16 (and QKV pack)
// ----------------------------------------------------------------------------
__global__ void tohalf(const float* __restrict__ in, __half* __restrict__ out, int n)
{
    int i = (blockIdx.x * blockDim.x + threadIdx.x) * 8;
    if (i < n) {
        float4 a = *(const float4*)(in + i);
        float4 b = *(const float4*)(in + i + 4);
        half2 h0 = __floats2half2_rn(a.x, a.y);
        half2 h1 = __floats2half2_rn(a.z, a.w);
        half2 h2 = __floats2half2_rn(b.x, b.y);
        half2 h3 = __floats2half2_rn(b.z, b.w);
        uint4 u;
        u.x = *(uint32_t*)&h0; u.y = *(uint32_t*)&h1;
        u.z = *(uint32_t*)&h2; u.w = *(uint32_t*)&h3;
        *(uint4*)(out + i) = u;
    }
}
__global__ void pack_qkv_h(const float* __restrict__ Wq, const float* __restrict__ Wk,
                           const float* __restrict__ Wv, __half* __restrict__ out)
{
    int i = (blockIdx.x * blockDim.x + threadIdx.x) * 8;   // over EMB*EMB
    int k = i >> 10;
    int n = i & 1023;
    __half* o = out + (size_t)k * QKVN + n;
    const float* srcs[3] = {Wq + i, Wk + i, Wv + i};
    #pragma unroll
    for (int m = 0; m < 3; m++) {
        float4 a = *(const float4*)(srcs[m]);
        float4 b = *(const float4*)(srcs[m] + 4);
        half2 h0 = __floats2half2_rn(a.x, a.y), h1 = __floats2half2_rn(a.z, a.w);
        half2 h2 = __floats2half2_rn(b.x, b.y), h3 = __floats2half2_rn(b.z, b.w);
        uint4 u;
        u.x = *(uint32_t*)&h0; u.y = *(uint32_t*)&h1;
        u.z = *(uint32_t*)&h2; u.w = *(uint32_t*)&h3;
        *(uint4*)(o + m * EMB) = u;
    }
}

// ----------------------------------------------------------------------------
// fp16 mma.sync GEMM, BK=64, 3-stage cp.async pipeline (R10 config).
// CTA 256x128, 512 threads (16 warps, 4Mx4N), warp tile 64x32.
// flags: 1 = gelu, 2 = fp16 output
// ----------------------------------------------------------------------------
#define BK 64
#define BM 256
#define AP 72
#define BPH 136
#define NSTG 3
#define A_STGH (BM * AP)
#define B_STGH (BK * BPH)
#define STG_H (A_STGH + B_STGH)
#define GEMM_SMEM (NSTG * STG_H * 2)

__global__ void __launch_bounds__(512, 1)
gemm_mma(const __half* __restrict__ A, const __half* __restrict__ B,
         const float* __restrict__ bias, const float* __restrict__ res,
         void* __restrict__ Cout, int N, int K, int flags)
{
    extern __shared__ __half smh[];

    const int tid  = threadIdx.x;
    const int lane = tid & 31;
    const int warp = tid >> 5;
    const int wm   = warp & 3;
    const int wn   = warp >> 2;
    const int brow = blockIdx.y * BM;
    const int bcol = blockIdx.x * 128;
    const int g = lane >> 2, t = lane & 3;

    float acc[4][4][4];
    #pragma unroll
    for (int mt = 0; mt < 4; mt++)
        #pragma unroll
        for (int nt = 0; nt < 4; nt++)
            #pragma unroll
            for (int e = 0; e < 4; e++) acc[mt][nt][e] = 0.f;

    const int nk = K / BK;

    auto load_stage = [&](int st, int k0) {
        __half* as = smh + st * STG_H;
        __half* bs = as + A_STGH;
        #pragma unroll
        for (int i = 0; i < 4; i++) {
            int id = tid + i * 512;
            int row = id >> 3, c = (id & 7) * 8;
            cp16(as + row * AP + c, A + (size_t)(brow + row) * K + k0 + c);
        }
        #pragma unroll
        for (int i = 0; i < 2; i++) {
            int id = tid + i * 512;
            int row = id >> 4, c = (id & 15) * 8;
            cp16(bs + row * BPH + c, B + (size_t)(k0 + row) * N + bcol + c);
        }
        asm volatile("cp.async.commit_group;" ::: "memory");
    };

    load_stage(0, 0);
    load_stage(1, BK);

    const int lr = lane & 15;
    const int lc = (lane >> 4) * 8;
    const int br = lane & 7;
    const int bseg = lane >> 3;

    int st = 0;
    for (int kt = 0; kt < nk; kt++) {
        asm volatile("cp.async.wait_group 1;" ::: "memory");
        __syncthreads();

        int nxt = kt + NSTG - 1;
        int nst = st + NSTG - 1; if (nst >= NSTG) nst -= NSTG;
        if (nxt < nk) load_stage(nst, nxt * BK);
        else asm volatile("cp.async.commit_group;" ::: "memory");

        const __half* as = smh + st * STG_H + (wm * 64) * AP;
        const __half* bs = smh + st * STG_H + A_STGH + wn * 32;

        #pragma unroll
        for (int ks = 0; ks < 4; ks++) {
            const int k = ks * 16;
            uint32_t af[4][4];
            #pragma unroll
            for (int mt = 0; mt < 4; mt++)
                ldsm_x4(af[mt], smem_u32(as + (mt * 16 + lr) * AP + k + lc));
            #pragma unroll
            for (int nbh = 0; nbh < 2; nbh++) {
                uint32_t bf[4];
                ldsm_x4t(bf, smem_u32(bs + (k + (bseg & 1) * 8 + br) * BPH
                                         + nbh * 16 + (bseg >> 1) * 8));
                #pragma unroll
                for (int mt = 0; mt < 4; mt++) {
                    mma16(acc[mt][nbh * 2],     af[mt], bf);
                    mma16(acc[mt][nbh * 2 + 1], af[mt], bf + 2);
                }
            }
        }
        if (++st == NSTG) st = 0;
    }

    // ---------------- epilogue (nt-outer: bias/gelu work hoisted over mt) ----
    #pragma unroll
    for (int nt = 0; nt < 4; nt++) {
        int col = bcol + wn * 32 + nt * 8 + t * 2;
        float b0 = 0.f, b1 = 0.f;
        if (bias) { b0 = __ldg(bias + col); b1 = __ldg(bias + col + 1); }
        #pragma unroll
        for (int mt = 0; mt < 4; mt++) {
            int r0 = brow + wm * 64 + mt * 16 + g;
            float v0 = acc[mt][nt][0] + b0, v1 = acc[mt][nt][1] + b1;
            float v2 = acc[mt][nt][2] + b0, v3 = acc[mt][nt][3] + b1;
            if (flags & 1) {
                v0 = gelu_tanh(v0); v1 = gelu_tanh(v1);
                v2 = gelu_tanh(v2); v3 = gelu_tanh(v3);
            }
            size_t i0 = (size_t)r0 * N + col;
            size_t i1 = (size_t)(r0 + 8) * N + col;
            if (res) {
                float2 r0v = *(const float2*)(res + i0);
                float2 r1v = *(const float2*)(res + i1);
                v0 += r0v.x; v1 += r0v.y; v2 += r1v.x; v3 += r1v.y;
            }
            if (flags & 2) {
                *(half2*)((__half*)Cout + i0) = __floats2half2_rn(v0, v1);
                *(half2*)((__half*)Cout + i1) = __floats2half2_rn(v2, v3);
            } else {
                *(float2*)((float*)Cout + i0) = make_float2(v0, v1);
                *(float2*)((float*)Cout + i1) = make_float2(v2, v3);
            }
        }
    }
}

// ----------------------------------------------------------------------------
// fp16 tensor-core causal flash attention (QT=64, R10 configuration)
// ----------------------------------------------------------------------------
#define HP 72
#define TILE_H (64 * HP)
#define ATTN_SMEM (5 * TILE_H * 2)

__global__ void __launch_bounds__(128)
attn_mma(const __half* __restrict__ qkv, __half* __restrict__ ctx)
{
    extern __shared__ __half smh[];
    __half* Qsh = smh;
    __half* Ksh = smh + TILE_H;
    __half* Vsh = Ksh + 2 * TILE_H;

    const int bh = blockIdx.x;
    const int qb = gridDim.y - 1 - blockIdx.y;   // heavy tiles first
    const int b = bh >> 4, h = bh & 15;
    const int tid = threadIdx.x, lane = tid & 31, w = tid >> 5;
    const int g = lane >> 2, t = lane & 3;
    const int lr = lane & 15, lc = (lane >> 4) * 8;
    const int br = lane & 7, bseg = lane >> 3;

    const __half* qbase = qkv + ((size_t)(b * SEQ + qb * 64)) * QKVN + h * HDIM;
    for (int i = tid; i < 64 * 8; i += 128) {
        int r = i >> 3, c = i & 7;
        *(uint4*)(Qsh + r * HP + c * 8) = *(const uint4*)(qbase + (size_t)r * QKVN + c * 8);
    }
    __syncthreads();

    uint32_t qf[4][4];
    #pragma unroll
    for (int kc = 0; kc < 4; kc++)
        ldsm_x4(qf[kc], smem_u32(Qsh + (w * 16 + lr) * HP + kc * 16 + lc));
    __syncthreads();

    float oacc[8][4];
    #pragma unroll
    for (int nt = 0; nt < 8; nt++)
        #pragma unroll
        for (int e = 0; e < 4; e++) oacc[nt][e] = 0.f;

    float m_lo = -INFINITY, m_hi = -INFINITY, l_lo = 0.f, l_hi = 0.f;
    const float scale = 0.125f;

    auto load_kv = [&](int kt, int st) {
        const __half* kb = qkv + ((size_t)(b * SEQ + kt * 64)) * QKVN + h * HDIM + EMB;
        const __half* vb = kb + EMB;
        __half* ks = Ksh + st * TILE_H;
        __half* vs = Vsh + st * TILE_H;
        for (int i = tid; i < 64 * 8; i += 128) {
            int r = i >> 3, c = i & 7;
            cp16(ks + r * HP + c * 8, kb + (size_t)r * QKVN + c * 8);
            cp16(vs + r * HP + c * 8, vb + (size_t)r * QKVN + c * 8);
        }
        asm volatile("cp.async.commit_group;" ::: "memory");
    };

    load_kv(0, 0);

    __half* Pw = Qsh + (w * 16) * HP;

    for (int kt = 0; kt <= qb; kt++) {
        int st = kt & 1;
        if (kt < qb) {
            load_kv(kt + 1, st ^ 1);
            asm volatile("cp.async.wait_group 1;" ::: "memory");
        } else {
            asm volatile("cp.async.wait_group 0;" ::: "memory");
        }
        __syncthreads();

        const __half* ks = Ksh + st * TILE_H;
        const __half* vs = Vsh + st * TILE_H;

        float sacc[8][4];
        #pragma unroll
        for (int nt = 0; nt < 8; nt++)
            #pragma unroll
            for (int e = 0; e < 4; e++) sacc[nt][e] = 0.f;
        #pragma unroll
        for (int kc = 0; kc < 4; kc++) {
            #pragma unroll
            for (int nb = 0; nb < 4; nb++) {
                uint32_t kf[4];
                ldsm_x4(kf, smem_u32(ks + (nb * 16 + (bseg >> 1) * 8 + br) * HP
                                        + kc * 16 + (bseg & 1) * 8));
                mma16(sacc[nb * 2],     qf[kc], kf);
                mma16(sacc[nb * 2 + 1], qf[kc], kf + 2);
            }
        }

        float tl = -INFINITY, th = -INFINITY;
        const int row_lo = w * 16 + g;
        const int row_hi = row_lo + 8;
        #pragma unroll
        for (int nt = 0; nt < 8; nt++) {
            float s0 = sacc[nt][0] * scale;
            float s1 = sacc[nt][1] * scale;
            float s2 = sacc[nt][2] * scale;
            float s3 = sacc[nt][3] * scale;
            if (kt == qb) {
                int c0 = nt * 8 + t * 2, c1 = c0 + 1;
                if (c0 > row_lo) s0 = -INFINITY;
                if (c1 > row_lo) s1 = -INFINITY;
                if (c0 > row_hi) s2 = -INFINITY;
                if (c1 > row_hi) s3 = -INFINITY;
            }
            sacc[nt][0] = s0; sacc[nt][1] = s1; sacc[nt][2] = s2; sacc[nt][3] = s3;
            tl = fmaxf(tl, fmaxf(s0, s1));
            th = fmaxf(th, fmaxf(s2, s3));
        }
        tl = fmaxf(tl, __shfl_xor_sync(0xffffffffu, tl, 1));
        tl = fmaxf(tl, __shfl_xor_sync(0xffffffffu, tl, 2));
        th = fmaxf(th, __shfl_xor_sync(0xffffffffu, th, 1));
        th = fmaxf(th, __shfl_xor_sync(0xffffffffu, th, 2));

        float mn_lo = fmaxf(m_lo, tl);
        float mn_hi = fmaxf(m_hi, th);
        float c_lo = __expf(m_lo - mn_lo);
        float c_hi = __expf(m_hi - mn_hi);

        float sl = 0.f, sh2 = 0.f;
        #pragma unroll
        for (int nt = 0; nt < 8; nt++) {
            float p0 = __expf(sacc[nt][0] - mn_lo);
            float p1 = __expf(sacc[nt][1] - mn_lo);
            float p2 = __expf(sacc[nt][2] - mn_hi);
            float p3 = __expf(sacc[nt][3] - mn_hi);
            sl += p0 + p1; sh2 += p2 + p3;
            int c = nt * 8 + t * 2;
            *(half2*)&Pw[g * HP + c]       = __floats2half2_rn(p0, p1);
            *(half2*)&Pw[(g + 8) * HP + c] = __floats2half2_rn(p2, p3);
        }
        sl  += __shfl_xor_sync(0xffffffffu, sl, 1);
        sl  += __shfl_xor_sync(0xffffffffu, sl, 2);
        sh2 += __shfl_xor_sync(0xffffffffu, sh2, 1);
        sh2 += __shfl_xor_sync(0xffffffffu, sh2, 2);
        l_lo = l_lo * c_lo + sl;
        l_hi = l_hi * c_hi + sh2;
        m_lo = mn_lo; m_hi = mn_hi;

        #pragma unroll
        for (int nt = 0; nt < 8; nt++) {
            oacc[nt][0] *= c_lo; oacc[nt][1] *= c_lo;
            oacc[nt][2] *= c_hi; oacc[nt][3] *= c_hi;
        }
        __syncwarp();

        #pragma unroll
        for (int kc = 0; kc < 4; kc++) {
            uint32_t pf[4];
            ldsm_x4(pf, smem_u32(Pw + lr * HP + kc * 16 + lc));
            #pragma unroll
            for (int nb = 0; nb < 4; nb++) {
                uint32_t vf[4];
                ldsm_x4t(vf, smem_u32(vs + (kc * 16 + (bseg & 1) * 8 + br) * HP
                                         + nb * 16 + (bseg >> 1) * 8));
                mma16(oacc[nb * 2],     pf, vf);
                mma16(oacc[nb * 2 + 1], pf, vf + 2);
            }
        }
        __syncthreads();
    }

    float inv_lo = 1.f / l_lo, inv_hi = 1.f / l_hi;
    __half* ob = ctx + ((size_t)(b * SEQ + qb * 64 + w * 16)) * EMB + h * HDIM;
    #pragma unroll
    for (int nt = 0; nt < 8; nt++) {
        int c = nt * 8 + t * 2;
        *(half2*)(ob + (size_t)g * EMB + c) =
            __floats2half2_rn(oacc[nt][0] * inv_lo, oacc[nt][1] * inv_lo);
        *(half2*)(ob + (size_t)(g + 8) * EMB + c) =
            __floats2half2_rn(oacc[nt][2] * inv_hi, oacc[nt][3] * inv_hi);
    }
}

// ----------------------------------------------------------------------------
// Launch — weight prep on side stream via legal capture fork (evRoot)
// ----------------------------------------------------------------------------
extern "C" void kernel_launch(void* const* d_in, const int* in_sizes, int n_in,
                              void* d_out, int out_size)
{
    const float* x    = (const float*)d_in[0];
    const float* Wq   = (const float*)d_in[1];
    const float* Wk   = (const float*)d_in[2];
    const float* Wv   = (const float*)d_in[3];
    const float* Wo   = (const float*)d_in[4];
    const float* bo   = (const float*)d_in[5];
    const float* W1   = (const float*)d_in[6];
    const float* b1   = (const float*)d_in[7];
    const float* W2   = (const float*)d_in[8];
    const float* b2   = (const float*)d_in[9];
    const float* ln1s = (const float*)d_in[10];
    const float* ln1b = (const float*)d_in[11];
    const float* ln2s = (const float*)d_in[12];
    const float* ln2b = (const float*)d_in[13];
    float* out = (float*)d_out;

    __half *h_p, *qkv_p, *ctx_p, *ff_p, *wqkv_p, *wo_p, *w1_p, *w2_p;
    float *x1_p;
    cudaGetSymbolAddress((void**)&h_p,    g_h);
    cudaGetSymbolAddress((void**)&qkv_p,  g_qkv);
    cudaGetSymbolAddress((void**)&ctx_p,  g_ctx);
    cudaGetSymbolAddress((void**)&x1_p,   g_x1);
    cudaGetSymbolAddress((void**)&ff_p,   g_ff);
    cudaGetSymbolAddress((void**)&wqkv_p, g_wqkv);
    cudaGetSymbolAddress((void**)&wo_p,   g_wo);
    cudaGetSymbolAddress((void**)&w1_p,   g_w1);
    cudaGetSymbolAddress((void**)&w2_p,   g_w2);

    cudaFuncSetAttribute(gemm_mma, cudaFuncAttributeMaxDynamicSharedMemorySize, GEMM_SMEM);
    cudaFuncSetAttribute(attn_mma, cudaFuncAttributeMaxDynamicSharedMemorySize, ATTN_SMEM);

    cudaStream_t s2;
    cudaStreamCreateWithFlags(&s2, cudaStreamNonBlocking);
    cudaEvent_t evRoot, evQKVw, evW;
    cudaEventCreateWithFlags(&evRoot, cudaEventDisableTiming);
    cudaEventCreateWithFlags(&evQKVw, cudaEventDisableTiming);
    cudaEventCreateWithFlags(&evW,    cudaEventDisableTiming);

    // legal capture fork: record on origin stream, side stream waits on it
    cudaEventRecord(evRoot, 0);
    cudaStreamWaitEvent(s2, evRoot, 0);

    // side stream: weight prep
    pack_qkv_h<<<(EMB * EMB / 8 + 255) / 256, 256, 0, s2>>>(Wq, Wk, Wv, wqkv_p);
    cudaEventRecord(evQKVw, s2);
    tohalf<<<(EMB * EMB / 8 + 255) / 256, 256, 0, s2>>>(Wo, wo_p, EMB * EMB);
    tohalf<<<(EMB * FFDIM / 8 + 255) / 256, 256, 0, s2>>>(W1, w1_p, EMB * FFDIM);
    tohalf<<<(EMB * FFDIM / 8 + 255) / 256, 256, 0, s2>>>(W2, w2_p, FFDIM * EMB);
    cudaEventRecord(evW, s2);

    // main stream
    ln_kernel<<<MROWS, 256>>>(x, ln1s, ln1b, h_p);

    dim3 gqkv(QKVN / 128, MROWS / BM);
    dim3 g1024(EMB / 128, MROWS / BM);
    dim3 g4096(FFDIM / 128, MROWS / BM);

    cudaStreamWaitEvent(0, evQKVw, 0);
    gemm_mma<<<gqkv, 512, GEMM_SMEM>>>(h_p, wqkv_p, nullptr, nullptr, qkv_p,
                                       QKVN, EMB, 2);

    dim3 attn_grid(BATCH * HEADS, SEQ / 64);
    attn_mma<<<attn_grid, 128, ATTN_SMEM>>>(qkv_p, ctx_p);

    cudaStreamWaitEvent(0, evW, 0);
    gemm_mma<<<g1024, 512, GEMM_SMEM>>>(ctx_p, wo_p, bo, x, x1_p, EMB, EMB, 0);

    ln_kernel<<<MROWS, 256>>>(x1_p, ln2s, ln2b, h_p);

    gemm_mma<<<g4096, 512, GEMM_SMEM>>>(h_p, w1_p, b1, nullptr, ff_p, FFDIM, EMB, 3);

    gemm_mma<<<g1024, 512, GEMM_SMEM>>>(ff_p, w2_p, b2, x1_p, out, EMB, FFDIM, 0);
}

// round 16
// speedup vs baseline: 1.0418x; 1.0418x over previous
#include <cuda_runtime.h>
#include <cuda_fp16.h>
#include <math.h>
#include <stdint.h>

#define BATCH 2
#define SEQ   2048
#define EMB   1024
#define HEADS 16
#define HDIM  64
#define FFDIM 4096
#define MROWS (BATCH * SEQ)   // 4096
#define QKVN  (3 * EMB)       // 3072

// ----------------------------------------------------------------------------
// Scratch (device globals — no runtime allocation allowed)
// ----------------------------------------------------------------------------
__device__ __half g_h   [MROWS * EMB];
__device__ __half g_qkv [MROWS * QKVN];
__device__ __half g_ctx [MROWS * EMB];
__device__ float  g_x1  [MROWS * EMB];
__device__ __half g_ff  [MROWS * FFDIM];
__device__ __half g_wqkv[EMB * QKVN];
__device__ __half g_wo  [EMB * EMB];
__device__ __half g_w1  [EMB * FFDIM];
__device__ __half g_w2  [FFDIM * EMB];

// ----------------------------------------------------------------------------
// Helpers
// ----------------------------------------------------------------------------
__device__ __forceinline__ uint32_t smem_u32(const void* p) {
    uint32_t a;
    asm("{ .reg .u64 t; cvta.to.shared.u64 t, %1; cvt.u32.u64 %0, t; }" : "=r"(a) : "l"(p));
    return a;
}
__device__ __forceinline__ void cp16(void* dst, const void* src) {
    asm volatile("cp.async.cg.shared.global [%0], [%1], 16;"
                 :: "r"(smem_u32(dst)), "l"(src) : "memory");
}
__device__ __forceinline__ float ex2(float x) {
    float r; asm("ex2.approx.ftz.f32 %0, %1;" : "=f"(r) : "f"(x)); return r;
}
// gelu_tanh == x * sigmoid(2u), u = c*(x + 0.044715 x^3). Same function, cheap.
__device__ __forceinline__ float gelu_tanh(float x) {
    float u2 = 1.5957691216f * x * (1.0f + 0.044715f * x * x);   // = 2u
    return __fdividef(x, 1.0f + __expf(-u2));
}
__device__ __forceinline__ void ldsm_x4(uint32_t* r, uint32_t addr) {
    asm volatile("ldmatrix.sync.aligned.m8n8.x4.shared.b16 {%0,%1,%2,%3}, [%4];"
                 : "=r"(r[0]), "=r"(r[1]), "=r"(r[2]), "=r"(r[3]) : "r"(addr));
}
__device__ __forceinline__ void ldsm_x4t(uint32_t* r, uint32_t addr) {
    asm volatile("ldmatrix.sync.aligned.m8n8.x4.trans.shared.b16 {%0,%1,%2,%3}, [%4];"
                 : "=r"(r[0]), "=r"(r[1]), "=r"(r[2]), "=r"(r[3]) : "r"(addr));
}
__device__ __forceinline__ void mma16(float* c, const uint32_t* a, const uint32_t* b) {
    asm volatile(
        "mma.sync.aligned.m16n8k16.row.col.f32.f16.f16.f32 "
        "{%0,%1,%2,%3}, {%4,%5,%6,%7}, {%8,%9}, {%0,%1,%2,%3};"
        : "+f"(c[0]), "+f"(c[1]), "+f"(c[2]), "+f"(c[3])
        : "r"(a[0]), "r"(a[1]), "r"(a[2]), "r"(a[3]), "r"(b[0]), "r"(b[1]));
}

// ----------------------------------------------------------------------------
// LayerNorm: fp32 in, fp16 out
// ----------------------------------------------------------------------------
__inline__ __device__ float warp_sum(float v) {
    #pragma unroll
    for (int o = 16; o > 0; o >>= 1) v += __shfl_xor_sync(0xffffffffu, v, o);
    return v;
}
__global__ void ln_kernel(const float* __restrict__ x,
                          const float* __restrict__ scale,
                          const float* __restrict__ shift,
                          __half* __restrict__ out)
{
    __shared__ float ssum[8], ssq[8];
    int row = blockIdx.x;
    int t = threadIdx.x;
    const float4* xr = (const float4*)(x + (size_t)row * EMB);
    float4 v = xr[t];
    float s  = v.x + v.y + v.z + v.w;
    float sq = v.x * v.x + v.y * v.y + v.z * v.z + v.w * v.w;
    float ws  = warp_sum(s);
    float wsq = warp_sum(sq);
    int lane = t & 31, wid = t >> 5;
    if (lane == 0) { ssum[wid] = ws; ssq[wid] = wsq; }
    __syncthreads();
    float tot = 0.f, totsq = 0.f;
    #pragma unroll
    for (int i = 0; i < 8; i++) { tot += ssum[i]; totsq += ssq[i]; }
    float mean = tot * (1.0f / EMB);
    float var  = totsq * (1.0f / EMB) - mean * mean;
    float inv  = rsqrtf(var + 1e-5f);
    float4 sc = ((const float4*)scale)[t];
    float4 sh = ((const float4*)shift)[t];
    __half* op = out + (size_t)row * EMB + t * 4;
    *(half2*)op       = __floats2half2_rn(sc.x * (v.x - mean) * inv + sh.x,
                                          sc.y * (v.y - mean) * inv + sh.y);
    *(half2*)(op + 2) = __floats2half2_rn(sc.z * (v.z - mean) * inv + sh.z,
                                          sc.w * (v.w - mean) * inv + sh.w);
}

// ----------------------------------------------------------------------------
// Weight prep: fp32 -> fp16 (and QKV pack)
// ----------------------------------------------------------------------------
__global__ void tohalf(const float* __restrict__ in, __half* __restrict__ out, int n)
{
    int i = (blockIdx.x * blockDim.x + threadIdx.x) * 8;
    if (i < n) {
        float4 a = *(const float4*)(in + i);
        float4 b = *(const float4*)(in + i + 4);
        half2 h0 = __floats2half2_rn(a.x, a.y);
        half2 h1 = __floats2half2_rn(a.z, a.w);
        half2 h2 = __floats2half2_rn(b.x, b.y);
        half2 h3 = __floats2half2_rn(b.z, b.w);
        uint4 u;
        u.x = *(uint32_t*)&h0; u.y = *(uint32_t*)&h1;
        u.z = *(uint32_t*)&h2; u.w = *(uint32_t*)&h3;
        *(uint4*)(out + i) = u;
    }
}
__global__ void pack_qkv_h(const float* __restrict__ Wq, const float* __restrict__ Wk,
                           const float* __restrict__ Wv, __half* __restrict__ out)
{
    int i = (blockIdx.x * blockDim.x + threadIdx.x) * 8;   // over EMB*EMB
    int k = i >> 10;
    int n = i & 1023;
    __half* o = out + (size_t)k * QKVN + n;
    const float* srcs[3] = {Wq + i, Wk + i, Wv + i};
    #pragma unroll
    for (int m = 0; m < 3; m++) {
        float4 a = *(const float4*)(srcs[m]);
        float4 b = *(const float4*)(srcs[m] + 4);
        half2 h0 = __floats2half2_rn(a.x, a.y), h1 = __floats2half2_rn(a.z, a.w);
        half2 h2 = __floats2half2_rn(b.x, b.y), h3 = __floats2half2_rn(b.z, b.w);
        uint4 u;
        u.x = *(uint32_t*)&h0; u.y = *(uint32_t*)&h1;
        u.z = *(uint32_t*)&h2; u.w = *(uint32_t*)&h3;
        *(uint4*)(o + m * EMB) = u;
    }
}

// ----------------------------------------------------------------------------
// fp16 mma.sync GEMM, BK=64, 3-stage cp.async pipeline (R10 config, exact).
// CTA 256x128, 512 threads (16 warps, 4Mx4N), warp tile 64x32.
// flags: 1 = gelu, 2 = fp16 output
// ----------------------------------------------------------------------------
#define BK 64
#define BM 256
#define AP 72
#define BPH 136
#define NSTG 3
#define A_STGH (BM * AP)
#define B_STGH (BK * BPH)
#define STG_H (A_STGH + B_STGH)
#define GEMM_SMEM (NSTG * STG_H * 2)

__global__ void __launch_bounds__(512, 1)
gemm_mma(const __half* __restrict__ A, const __half* __restrict__ B,
         const float* __restrict__ bias, const float* __restrict__ res,
         void* __restrict__ Cout, int N, int K, int flags)
{
    extern __shared__ __half smh[];

    const int tid  = threadIdx.x;
    const int lane = tid & 31;
    const int warp = tid >> 5;
    const int wm   = warp & 3;
    const int wn   = warp >> 2;
    const int brow = blockIdx.y * BM;
    const int bcol = blockIdx.x * 128;
    const int g = lane >> 2, t = lane & 3;

    float acc[4][4][4];
    #pragma unroll
    for (int mt = 0; mt < 4; mt++)
        #pragma unroll
        for (int nt = 0; nt < 4; nt++)
            #pragma unroll
            for (int e = 0; e < 4; e++) acc[mt][nt][e] = 0.f;

    const int nk = K / BK;

    auto load_stage = [&](int st, int k0) {
        __half* as = smh + st * STG_H;
        __half* bs = as + A_STGH;
        #pragma unroll
        for (int i = 0; i < 4; i++) {
            int id = tid + i * 512;
            int row = id >> 3, c = (id & 7) * 8;
            cp16(as + row * AP + c, A + (size_t)(brow + row) * K + k0 + c);
        }
        #pragma unroll
        for (int i = 0; i < 2; i++) {
            int id = tid + i * 512;
            int row = id >> 4, c = (id & 15) * 8;
            cp16(bs + row * BPH + c, B + (size_t)(k0 + row) * N + bcol + c);
        }
        asm volatile("cp.async.commit_group;" ::: "memory");
    };

    load_stage(0, 0);
    load_stage(1, BK);

    const int lr = lane & 15;
    const int lc = (lane >> 4) * 8;
    const int br = lane & 7;
    const int bseg = lane >> 3;

    int st = 0;
    for (int kt = 0; kt < nk; kt++) {
        asm volatile("cp.async.wait_group 1;" ::: "memory");
        __syncthreads();

        int nxt = kt + NSTG - 1;
        int nst = st + NSTG - 1; if (nst >= NSTG) nst -= NSTG;
        if (nxt < nk) load_stage(nst, nxt * BK);
        else asm volatile("cp.async.commit_group;" ::: "memory");

        const __half* as = smh + st * STG_H + (wm * 64) * AP;
        const __half* bs = smh + st * STG_H + A_STGH + wn * 32;

        #pragma unroll
        for (int ks = 0; ks < 4; ks++) {
            const int k = ks * 16;
            uint32_t af[4][4];
            #pragma unroll
            for (int mt = 0; mt < 4; mt++)
                ldsm_x4(af[mt], smem_u32(as + (mt * 16 + lr) * AP + k + lc));
            #pragma unroll
            for (int nbh = 0; nbh < 2; nbh++) {
                uint32_t bf[4];
                ldsm_x4t(bf, smem_u32(bs + (k + (bseg & 1) * 8 + br) * BPH
                                         + nbh * 16 + (bseg >> 1) * 8));
                #pragma unroll
                for (int mt = 0; mt < 4; mt++) {
                    mma16(acc[mt][nbh * 2],     af[mt], bf);
                    mma16(acc[mt][nbh * 2 + 1], af[mt], bf + 2);
                }
            }
        }
        if (++st == NSTG) st = 0;
    }

    // ---------------- epilogue (R10 exact: mt-outer) ----------------
    #pragma unroll
    for (int mt = 0; mt < 4; mt++) {
        int r0 = brow + wm * 64 + mt * 16 + g;
        #pragma unroll
        for (int nt = 0; nt < 4; nt++) {
            int col = bcol + wn * 32 + nt * 8 + t * 2;
            float v0 = acc[mt][nt][0], v1 = acc[mt][nt][1];
            float v2 = acc[mt][nt][2], v3 = acc[mt][nt][3];
            if (bias) {
                float b0 = __ldg(bias + col), b1 = __ldg(bias + col + 1);
                v0 += b0; v1 += b1; v2 += b0; v3 += b1;
            }
            if (flags & 1) {
                v0 = gelu_tanh(v0); v1 = gelu_tanh(v1);
                v2 = gelu_tanh(v2); v3 = gelu_tanh(v3);
            }
            size_t i0 = (size_t)r0 * N + col;
            size_t i1 = (size_t)(r0 + 8) * N + col;
            if (res) {
                float2 r0v = *(const float2*)(res + i0);
                float2 r1v = *(const float2*)(res + i1);
                v0 += r0v.x; v1 += r0v.y; v2 += r1v.x; v3 += r1v.y;
            }
            if (flags & 2) {
                *(half2*)((__half*)Cout + i0) = __floats2half2_rn(v0, v1);
                *(half2*)((__half*)Cout + i1) = __floats2half2_rn(v2, v3);
            } else {
                *(float2*)((float*)Cout + i0) = make_float2(v0, v1);
                *(float2*)((float*)Cout + i1) = make_float2(v2, v3);
            }
        }
    }
}

// ----------------------------------------------------------------------------
// fp16 tensor-core causal flash attention (QT=64; scores kept in log2 domain:
// scale folded with log2e, softmax via raw ex2 — one FMUL fewer per element)
// ----------------------------------------------------------------------------
#define HP 72
#define TILE_H (64 * HP)
#define ATTN_SMEM (5 * TILE_H * 2)

__global__ void __launch_bounds__(128)
attn_mma(const __half* __restrict__ qkv, __half* __restrict__ ctx)
{
    extern __shared__ __half smh[];
    __half* Qsh = smh;
    __half* Ksh = smh + TILE_H;
    __half* Vsh = Ksh + 2 * TILE_H;

    const int bh = blockIdx.x;
    const int qb = gridDim.y - 1 - blockIdx.y;   // heavy tiles first
    const int b = bh >> 4, h = bh & 15;
    const int tid = threadIdx.x, lane = tid & 31, w = tid >> 5;
    const int g = lane >> 2, t = lane & 3;
    const int lr = lane & 15, lc = (lane >> 4) * 8;
    const int br = lane & 7, bseg = lane >> 3;

    const __half* qbase = qkv + ((size_t)(b * SEQ + qb * 64)) * QKVN + h * HDIM;
    for (int i = tid; i < 64 * 8; i += 128) {
        int r = i >> 3, c = i & 7;
        *(uint4*)(Qsh + r * HP + c * 8) = *(const uint4*)(qbase + (size_t)r * QKVN + c * 8);
    }
    __syncthreads();

    uint32_t qf[4][4];
    #pragma unroll
    for (int kc = 0; kc < 4; kc++)
        ldsm_x4(qf[kc], smem_u32(Qsh + (w * 16 + lr) * HP + kc * 16 + lc));
    __syncthreads();

    float oacc[8][4];
    #pragma unroll
    for (int nt = 0; nt < 8; nt++)
        #pragma unroll
        for (int e = 0; e < 4; e++) oacc[nt][e] = 0.f;

    float m_lo = -INFINITY, m_hi = -INFINITY, l_lo = 0.f, l_hi = 0.f;
    const float scale2 = 0.125f * 1.44269504089f;   // (1/sqrt(64)) * log2(e)

    auto load_kv = [&](int kt, int st) {
        const __half* kb = qkv + ((size_t)(b * SEQ + kt * 64)) * QKVN + h * HDIM + EMB;
        const __half* vb = kb + EMB;
        __half* ks = Ksh + st * TILE_H;
        __half* vs = Vsh + st * TILE_H;
        for (int i = tid; i < 64 * 8; i += 128) {
            int r = i >> 3, c = i & 7;
            cp16(ks + r * HP + c * 8, kb + (size_t)r * QKVN + c * 8);
            cp16(vs + r * HP + c * 8, vb + (size_t)r * QKVN + c * 8);
        }
        asm volatile("cp.async.commit_group;" ::: "memory");
    };

    load_kv(0, 0);

    __half* Pw = Qsh + (w * 16) * HP;

    for (int kt = 0; kt <= qb; kt++) {
        int st = kt & 1;
        if (kt < qb) {
            load_kv(kt + 1, st ^ 1);
            asm volatile("cp.async.wait_group 1;" ::: "memory");
        } else {
            asm volatile("cp.async.wait_group 0;" ::: "memory");
        }
        __syncthreads();

        const __half* ks = Ksh + st * TILE_H;
        const __half* vs = Vsh + st * TILE_H;

        float sacc[8][4];
        #pragma unroll
        for (int nt = 0; nt < 8; nt++)
            #pragma unroll
            for (int e = 0; e < 4; e++) sacc[nt][e] = 0.f;
        #pragma unroll
        for (int kc = 0; kc < 4; kc++) {
            #pragma unroll
            for (int nb = 0; nb < 4; nb++) {
                uint32_t kf[4];
                ldsm_x4(kf, smem_u32(ks + (nb * 16 + (bseg >> 1) * 8 + br) * HP
                                        + kc * 16 + (bseg & 1) * 8));
                mma16(sacc[nb * 2],     qf[kc], kf);
                mma16(sacc[nb * 2 + 1], qf[kc], kf + 2);
            }
        }

        // scores in log2 domain: s2 = sacc * scale * log2e
        float tl = -INFINITY, th = -INFINITY;
        const int row_lo = w * 16 + g;
        const int row_hi = row_lo + 8;
        #pragma unroll
        for (int nt = 0; nt < 8; nt++) {
            float s0 = sacc[nt][0] * scale2;
            float s1 = sacc[nt][1] * scale2;
            float s2 = sacc[nt][2] * scale2;
            float s3 = sacc[nt][3] * scale2;
            if (kt == qb) {
                int c0 = nt * 8 + t * 2, c1 = c0 + 1;
                if (c0 > row_lo) s0 = -INFINITY;
                if (c1 > row_lo) s1 = -INFINITY;
                if (c0 > row_hi) s2 = -INFINITY;
                if (c1 > row_hi) s3 = -INFINITY;
            }
            sacc[nt][0] = s0; sacc[nt][1] = s1; sacc[nt][2] = s2; sacc[nt][3] = s3;
            tl = fmaxf(tl, fmaxf(s0, s1));
            th = fmaxf(th, fmaxf(s2, s3));
        }
        tl = fmaxf(tl, __shfl_xor_sync(0xffffffffu, tl, 1));
        tl = fmaxf(tl, __shfl_xor_sync(0xffffffffu, tl, 2));
        th = fmaxf(th, __shfl_xor_sync(0xffffffffu, th, 1));
        th = fmaxf(th, __shfl_xor_sync(0xffffffffu, th, 2));

        float mn_lo = fmaxf(m_lo, tl);
        float mn_hi = fmaxf(m_hi, th);
        float c_lo = ex2(m_lo - mn_lo);   // 2^(m_old - m_new), exact correction
        float c_hi = ex2(m_hi - mn_hi);

        float sl = 0.f, sh2 = 0.f;
        #pragma unroll
        for (int nt = 0; nt < 8; nt++) {
            float p0 = ex2(sacc[nt][0] - mn_lo);
            float p1 = ex2(sacc[nt][1] - mn_lo);
            float p2 = ex2(sacc[nt][2] - mn_hi);
            float p3 = ex2(sacc[nt][3] - mn_hi);
            sl += p0 + p1; sh2 += p2 + p3;
            int c = nt * 8 + t * 2;
            *(half2*)&Pw[g * HP + c]       = __floats2half2_rn(p0, p1);
            *(half2*)&Pw[(g + 8) * HP + c] = __floats2half2_rn(p2, p3);
        }
        sl  += __shfl_xor_sync(0xffffffffu, sl, 1);
        sl  += __shfl_xor_sync(0xffffffffu, sl, 2);
        sh2 += __shfl_xor_sync(0xffffffffu, sh2, 1);
        sh2 += __shfl_xor_sync(0xffffffffu, sh2, 2);
        l_lo = l_lo * c_lo + sl;
        l_hi = l_hi * c_hi + sh2;
        m_lo = mn_lo; m_hi = mn_hi;

        #pragma unroll
        for (int nt = 0; nt < 8; nt++) {
            oacc[nt][0] *= c_lo; oacc[nt][1] *= c_lo;
            oacc[nt][2] *= c_hi; oacc[nt][3] *= c_hi;
        }
        __syncwarp();

        #pragma unroll
        for (int kc = 0; kc < 4; kc++) {
            uint32_t pf[4];
            ldsm_x4(pf, smem_u32(Pw + lr * HP + kc * 16 + lc));
            #pragma unroll
            for (int nb = 0; nb < 4; nb++) {
                uint32_t vf[4];
                ldsm_x4t(vf, smem_u32(vs + (kc * 16 + (bseg & 1) * 8 + br) * HP
                                         + nb * 16 + (bseg >> 1) * 8));
                mma16(oacc[nb * 2],     pf, vf);
                mma16(oacc[nb * 2 + 1], pf, vf + 2);
            }
        }
        __syncthreads();
    }

    float inv_lo = 1.f / l_lo, inv_hi = 1.f / l_hi;
    __half* ob = ctx + ((size_t)(b * SEQ + qb * 64 + w * 16)) * EMB + h * HDIM;
    #pragma unroll
    for (int nt = 0; nt < 8; nt++) {
        int c = nt * 8 + t * 2;
        *(half2*)(ob + (size_t)g * EMB + c) =
            __floats2half2_rn(oacc[nt][0] * inv_lo, oacc[nt][1] * inv_lo);
        *(half2*)(ob + (size_t)(g + 8) * EMB + c) =
            __floats2half2_rn(oacc[nt][2] * inv_hi, oacc[nt][3] * inv_hi);
    }
}

// ----------------------------------------------------------------------------
// Launch — weight prep on side stream via legal capture fork (evRoot)
// ----------------------------------------------------------------------------
extern "C" void kernel_launch(void* const* d_in, const int* in_sizes, int n_in,
                              void* d_out, int out_size)
{
    const float* x    = (const float*)d_in[0];
    const float* Wq   = (const float*)d_in[1];
    const float* Wk   = (const float*)d_in[2];
    const float* Wv   = (const float*)d_in[3];
    const float* Wo   = (const float*)d_in[4];
    const float* bo   = (const float*)d_in[5];
    const float* W1   = (const float*)d_in[6];
    const float* b1   = (const float*)d_in[7];
    const float* W2   = (const float*)d_in[8];
    const float* b2   = (const float*)d_in[9];
    const float* ln1s = (const float*)d_in[10];
    const float* ln1b = (const float*)d_in[11];
    const float* ln2s = (const float*)d_in[12];
    const float* ln2b = (const float*)d_in[13];
    float* out = (float*)d_out;

    __half *h_p, *qkv_p, *ctx_p, *ff_p, *wqkv_p, *wo_p, *w1_p, *w2_p;
    float *x1_p;
    cudaGetSymbolAddress((void**)&h_p,    g_h);
    cudaGetSymbolAddress((void**)&qkv_p,  g_qkv);
    cudaGetSymbolAddress((void**)&ctx_p,  g_ctx);
    cudaGetSymbolAddress((void**)&x1_p,   g_x1);
    cudaGetSymbolAddress((void**)&ff_p,   g_ff);
    cudaGetSymbolAddress((void**)&wqkv_p, g_wqkv);
    cudaGetSymbolAddress((void**)&wo_p,   g_wo);
    cudaGetSymbolAddress((void**)&w1_p,   g_w1);
    cudaGetSymbolAddress((void**)&w2_p,   g_w2);

    cudaFuncSetAttribute(gemm_mma, cudaFuncAttributeMaxDynamicSharedMemorySize, GEMM_SMEM);
    cudaFuncSetAttribute(attn_mma, cudaFuncAttributeMaxDynamicSharedMemorySize, ATTN_SMEM);

    cudaStream_t s2;
    cudaStreamCreateWithFlags(&s2, cudaStreamNonBlocking);
    cudaEvent_t evRoot, evQKVw, evW;
    cudaEventCreateWithFlags(&evRoot, cudaEventDisableTiming);
    cudaEventCreateWithFlags(&evQKVw, cudaEventDisableTiming);
    cudaEventCreateWithFlags(&evW,    cudaEventDisableTiming);

    // legal capture fork: record on origin stream, side stream waits on it
    cudaEventRecord(evRoot, 0);
    cudaStreamWaitEvent(s2, evRoot, 0);

    // side stream: weight prep
    pack_qkv_h<<<(EMB * EMB / 8 + 255) / 256, 256, 0, s2>>>(Wq, Wk, Wv, wqkv_p);
    cudaEventRecord(evQKVw, s2);
    tohalf<<<(EMB * EMB / 8 + 255) / 256, 256, 0, s2>>>(Wo, wo_p, EMB * EMB);
    tohalf<<<(EMB * FFDIM / 8 + 255) / 256, 256, 0, s2>>>(W1, w1_p, EMB * FFDIM);
    tohalf<<<(EMB * FFDIM / 8 + 255) / 256, 256, 0, s2>>>(W2, w2_p, FFDIM * EMB);
    cudaEventRecord(evW, s2);

    // main stream
    ln_kernel<<<MROWS, 256>>>(x, ln1s, ln1b, h_p);

    dim3 gqkv(QKVN / 128, MROWS / BM);
    dim3 g1024(EMB / 128, MROWS / BM);
    dim3 g4096(FFDIM / 128, MROWS / BM);

    cudaStreamWaitEvent(0, evQKVw, 0);
    gemm_mma<<<gqkv, 512, GEMM_SMEM>>>(h_p, wqkv_p, nullptr, nullptr, qkv_p,
                                       QKVN, EMB, 2);

    dim3 attn_grid(BATCH * HEADS, SEQ / 64);
    attn_mma<<<attn_grid, 128, ATTN_SMEM>>>(qkv_p, ctx_p);

    cudaStreamWaitEvent(0, evW, 0);
    gemm_mma<<<g1024, 512, GEMM_SMEM>>>(ctx_p, wo_p, bo, x, x1_p, EMB, EMB, 0);

    ln_kernel<<<MROWS, 256>>>(x1_p, ln2s, ln2b, h_p);

    gemm_mma<<<g4096, 512, GEMM_SMEM>>>(h_p, w1_p, b1, nullptr, ff_p, FFDIM, EMB, 3);

    gemm_mma<<<g1024, 512, GEMM_SMEM>>>(ff_p, w2_p, b2, x1_p, out, EMB, FFDIM, 0);
}

// round 17
// speedup vs baseline: 1.0421x; 1.0003x over previous
#include <cuda_runtime.h>
#include <cuda_fp16.h>
#include <math.h>
#include <stdint.h>

#define BATCH 2
#define SEQ   2048
#define EMB   1024
#define HEADS 16
#define HDIM  64
#define FFDIM 4096
#define MROWS (BATCH * SEQ)   // 4096
#define QKVN  (3 * EMB)       // 3072

// ----------------------------------------------------------------------------
// Scratch (device globals — no runtime allocation allowed)
// ----------------------------------------------------------------------------
__device__ __half g_h   [MROWS * EMB];
__device__ __half g_qkv [MROWS * QKVN];
__device__ __half g_ctx [MROWS * EMB];
__device__ float  g_x1  [MROWS * EMB];
__device__ __half g_ff  [MROWS * FFDIM];
__device__ __half g_wqkv[EMB * QKVN];
__device__ __half g_wo  [EMB * EMB];
__device__ __half g_w1  [EMB * FFDIM];
__device__ __half g_w2  [FFDIM * EMB];

// ----------------------------------------------------------------------------
// Helpers
// ----------------------------------------------------------------------------
__device__ __forceinline__ uint32_t smem_u32(const void* p) {
    uint32_t a;
    asm("{ .reg .u64 t; cvta.to.shared.u64 t, %1; cvt.u32.u64 %0, t; }" : "=r"(a) : "l"(p));
    return a;
}
__device__ __forceinline__ void cp16(void* dst, const void* src) {
    asm volatile("cp.async.cg.shared.global [%0], [%1], 16;"
                 :: "r"(smem_u32(dst)), "l"(src) : "memory");
}
__device__ __forceinline__ float ex2(float x) {
    float r; asm("ex2.approx.ftz.f32 %0, %1;" : "=f"(r) : "f"(x)); return r;
}
// gelu_tanh == x * sigmoid(2u) with the exp kept in the log2 domain:
// 2.3022083 = 2 * 0.7978845608 * log2(e). One FMUL fewer than __expf path.
__device__ __forceinline__ float gelu_tanh(float x) {
    float e2 = 2.3022083f * x * (1.0f + 0.044715f * x * x);
    return __fdividef(x, 1.0f + ex2(-e2));
}
__device__ __forceinline__ void ldsm_x4(uint32_t* r, uint32_t addr) {
    asm volatile("ldmatrix.sync.aligned.m8n8.x4.shared.b16 {%0,%1,%2,%3}, [%4];"
                 : "=r"(r[0]), "=r"(r[1]), "=r"(r[2]), "=r"(r[3]) : "r"(addr));
}
__device__ __forceinline__ void ldsm_x4t(uint32_t* r, uint32_t addr) {
    asm volatile("ldmatrix.sync.aligned.m8n8.x4.trans.shared.b16 {%0,%1,%2,%3}, [%4];"
                 : "=r"(r[0]), "=r"(r[1]), "=r"(r[2]), "=r"(r[3]) : "r"(addr));
}
__device__ __forceinline__ void mma16(float* c, const uint32_t* a, const uint32_t* b) {
    asm volatile(
        "mma.sync.aligned.m16n8k16.row.col.f32.f16.f16.f32 "
        "{%0,%1,%2,%3}, {%4,%5,%6,%7}, {%8,%9}, {%0,%1,%2,%3};"
        : "+f"(c[0]), "+f"(c[1]), "+f"(c[2]), "+f"(c[3])
        : "r"(a[0]), "r"(a[1]), "r"(a[2]), "r"(a[3]), "r"(b[0]), "r"(b[1]));
}

// ----------------------------------------------------------------------------
// LayerNorm: fp32 in, fp16 out
// ----------------------------------------------------------------------------
__inline__ __device__ float warp_sum(float v) {
    #pragma unroll
    for (int o = 16; o > 0; o >>= 1) v += __shfl_xor_sync(0xffffffffu, v, o);
    return v;
}
__global__ void ln_kernel(const float* __restrict__ x,
                          const float* __restrict__ scale,
                          const float* __restrict__ shift,
                          __half* __restrict__ out)
{
    __shared__ float ssum[8], ssq[8];
    int row = blockIdx.x;
    int t = threadIdx.x;
    const float4* xr = (const float4*)(x + (size_t)row * EMB);
    float4 v = xr[t];
    float s  = v.x + v.y + v.z + v.w;
    float sq = v.x * v.x + v.y * v.y + v.z * v.z + v.w * v.w;
    float ws  = warp_sum(s);
    float wsq = warp_sum(sq);
    int lane = t & 31, wid = t >> 5;
    if (lane == 0) { ssum[wid] = ws; ssq[wid] = wsq; }
    __syncthreads();
    float tot = 0.f, totsq = 0.f;
    #pragma unroll
    for (int i = 0; i < 8; i++) { tot += ssum[i]; totsq += ssq[i]; }
    float mean = tot * (1.0f / EMB);
    float var  = totsq * (1.0f / EMB) - mean * mean;
    float inv  = rsqrtf(var + 1e-5f);
    float4 sc = ((const float4*)scale)[t];
    float4 sh = ((const float4*)shift)[t];
    __half* op = out + (size_t)row * EMB + t * 4;
    *(half2*)op       = __floats2half2_rn(sc.x * (v.x - mean) * inv + sh.x,
                                          sc.y * (v.y - mean) * inv + sh.y);
    *(half2*)(op + 2) = __floats2half2_rn(sc.z * (v.z - mean) * inv + sh.z,
                                          sc.w * (v.w - mean) * inv + sh.w);
}

// ----------------------------------------------------------------------------
// Weight prep: fp32 -> fp16 (and QKV pack)
// ----------------------------------------------------------------------------
__global__ void tohalf(const float* __restrict__ in, __half* __restrict__ out, int n)
{
    int i = (blockIdx.x * blockDim.x + threadIdx.x) * 8;
    if (i < n) {
        float4 a = *(const float4*)(in + i);
        float4 b = *(const float4*)(in + i + 4);
        half2 h0 = __floats2half2_rn(a.x, a.y);
        half2 h1 = __floats2half2_rn(a.z, a.w);
        half2 h2 = __floats2half2_rn(b.x, b.y);
        half2 h3 = __floats2half2_rn(b.z, b.w);
        uint4 u;
        u.x = *(uint32_t*)&h0; u.y = *(uint32_t*)&h1;
        u.z = *(uint32_t*)&h2; u.w = *(uint32_t*)&h3;
        *(uint4*)(out + i) = u;
    }
}
__global__ void pack_qkv_h(const float* __restrict__ Wq, const float* __restrict__ Wk,
                           const float* __restrict__ Wv, __half* __restrict__ out)
{
    int i = (blockIdx.x * blockDim.x + threadIdx.x) * 8;   // over EMB*EMB
    int k = i >> 10;
    int n = i & 1023;
    __half* o = out + (size_t)k * QKVN + n;
    const float* srcs[3] = {Wq + i, Wk + i, Wv + i};
    #pragma unroll
    for (int m = 0; m < 3; m++) {
        float4 a = *(const float4*)(srcs[m]);
        float4 b = *(const float4*)(srcs[m] + 4);
        half2 h0 = __floats2half2_rn(a.x, a.y), h1 = __floats2half2_rn(a.z, a.w);
        half2 h2 = __floats2half2_rn(b.x, b.y), h3 = __floats2half2_rn(b.z, b.w);
        uint4 u;
        u.x = *(uint32_t*)&h0; u.y = *(uint32_t*)&h1;
        u.z = *(uint32_t*)&h2; u.w = *(uint32_t*)&h3;
        *(uint4*)(o + m * EMB) = u;
    }
}

// ----------------------------------------------------------------------------
// fp16 mma.sync GEMM, BK=64, 3-stage cp.async pipeline (R10 config, exact).
// CTA 256x128, 512 threads (16 warps, 4Mx4N), warp tile 64x32.
// flags: 1 = gelu, 2 = fp16 output
// ----------------------------------------------------------------------------
#define BK 64
#define BM 256
#define AP 72
#define BPH 136
#define NSTG 3
#define A_STGH (BM * AP)
#define B_STGH (BK * BPH)
#define STG_H (A_STGH + B_STGH)
#define GEMM_SMEM (NSTG * STG_H * 2)

__global__ void __launch_bounds__(512, 1)
gemm_mma(const __half* __restrict__ A, const __half* __restrict__ B,
         const float* __restrict__ bias, const float* __restrict__ res,
         void* __restrict__ Cout, int N, int K, int flags)
{
    extern __shared__ __half smh[];

    const int tid  = threadIdx.x;
    const int lane = tid & 31;
    const int warp = tid >> 5;
    const int wm   = warp & 3;
    const int wn   = warp >> 2;
    const int brow = blockIdx.y * BM;
    const int bcol = blockIdx.x * 128;
    const int g = lane >> 2, t = lane & 3;

    float acc[4][4][4];
    #pragma unroll
    for (int mt = 0; mt < 4; mt++)
        #pragma unroll
        for (int nt = 0; nt < 4; nt++)
            #pragma unroll
            for (int e = 0; e < 4; e++) acc[mt][nt][e] = 0.f;

    const int nk = K / BK;

    auto load_stage = [&](int st, int k0) {
        __half* as = smh + st * STG_H;
        __half* bs = as + A_STGH;
        #pragma unroll
        for (int i = 0; i < 4; i++) {
            int id = tid + i * 512;
            int row = id >> 3, c = (id & 7) * 8;
            cp16(as + row * AP + c, A + (size_t)(brow + row) * K + k0 + c);
        }
        #pragma unroll
        for (int i = 0; i < 2; i++) {
            int id = tid + i * 512;
            int row = id >> 4, c = (id & 15) * 8;
            cp16(bs + row * BPH + c, B + (size_t)(k0 + row) * N + bcol + c);
        }
        asm volatile("cp.async.commit_group;" ::: "memory");
    };

    load_stage(0, 0);
    load_stage(1, BK);

    const int lr = lane & 15;
    const int lc = (lane >> 4) * 8;
    const int br = lane & 7;
    const int bseg = lane >> 3;

    int st = 0;
    for (int kt = 0; kt < nk; kt++) {
        asm volatile("cp.async.wait_group 1;" ::: "memory");
        __syncthreads();

        int nxt = kt + NSTG - 1;
        int nst = st + NSTG - 1; if (nst >= NSTG) nst -= NSTG;
        if (nxt < nk) load_stage(nst, nxt * BK);
        else asm volatile("cp.async.commit_group;" ::: "memory");

        const __half* as = smh + st * STG_H + (wm * 64) * AP;
        const __half* bs = smh + st * STG_H + A_STGH + wn * 32;

        #pragma unroll
        for (int ks = 0; ks < 4; ks++) {
            const int k = ks * 16;
            uint32_t af[4][4];
            #pragma unroll
            for (int mt = 0; mt < 4; mt++)
                ldsm_x4(af[mt], smem_u32(as + (mt * 16 + lr) * AP + k + lc));
            #pragma unroll
            for (int nbh = 0; nbh < 2; nbh++) {
                uint32_t bf[4];
                ldsm_x4t(bf, smem_u32(bs + (k + (bseg & 1) * 8 + br) * BPH
                                         + nbh * 16 + (bseg >> 1) * 8));
                #pragma unroll
                for (int mt = 0; mt < 4; mt++) {
                    mma16(acc[mt][nbh * 2],     af[mt], bf);
                    mma16(acc[mt][nbh * 2 + 1], af[mt], bf + 2);
                }
            }
        }
        if (++st == NSTG) st = 0;
    }

    // ---------------- epilogue (R10 exact: mt-outer) ----------------
    #pragma unroll
    for (int mt = 0; mt < 4; mt++) {
        int r0 = brow + wm * 64 + mt * 16 + g;
        #pragma unroll
        for (int nt = 0; nt < 4; nt++) {
            int col = bcol + wn * 32 + nt * 8 + t * 2;
            float v0 = acc[mt][nt][0], v1 = acc[mt][nt][1];
            float v2 = acc[mt][nt][2], v3 = acc[mt][nt][3];
            if (bias) {
                float b0 = __ldg(bias + col), b1 = __ldg(bias + col + 1);
                v0 += b0; v1 += b1; v2 += b0; v3 += b1;
            }
            if (flags & 1) {
                v0 = gelu_tanh(v0); v1 = gelu_tanh(v1);
                v2 = gelu_tanh(v2); v3 = gelu_tanh(v3);
            }
            size_t i0 = (size_t)r0 * N + col;
            size_t i1 = (size_t)(r0 + 8) * N + col;
            if (res) {
                float2 r0v = *(const float2*)(res + i0);
                float2 r1v = *(const float2*)(res + i1);
                v0 += r0v.x; v1 += r0v.y; v2 += r1v.x; v3 += r1v.y;
            }
            if (flags & 2) {
                *(half2*)((__half*)Cout + i0) = __floats2half2_rn(v0, v1);
                *(half2*)((__half*)Cout + i1) = __floats2half2_rn(v2, v3);
            } else {
                *(float2*)((float*)Cout + i0) = make_float2(v0, v1);
                *(float2*)((float*)Cout + i1) = make_float2(v2, v3);
            }
        }
    }
}

// ----------------------------------------------------------------------------
// fp16 tensor-core causal flash attention (QT=64; log2-domain softmax)
// ----------------------------------------------------------------------------
#define HP 72
#define TILE_H (64 * HP)
#define ATTN_SMEM (5 * TILE_H * 2)

__global__ void __launch_bounds__(128)
attn_mma(const __half* __restrict__ qkv, __half* __restrict__ ctx)
{
    extern __shared__ __half smh[];
    __half* Qsh = smh;
    __half* Ksh = smh + TILE_H;
    __half* Vsh = Ksh + 2 * TILE_H;

    const int bh = blockIdx.x;
    const int qb = gridDim.y - 1 - blockIdx.y;   // heavy tiles first
    const int b = bh >> 4, h = bh & 15;
    const int tid = threadIdx.x, lane = tid & 31, w = tid >> 5;
    const int g = lane >> 2, t = lane & 3;
    const int lr = lane & 15, lc = (lane >> 4) * 8;
    const int br = lane & 7, bseg = lane >> 3;

    const __half* qbase = qkv + ((size_t)(b * SEQ + qb * 64)) * QKVN + h * HDIM;
    for (int i = tid; i < 64 * 8; i += 128) {
        int r = i >> 3, c = i & 7;
        *(uint4*)(Qsh + r * HP + c * 8) = *(const uint4*)(qbase + (size_t)r * QKVN + c * 8);
    }
    __syncthreads();

    uint32_t qf[4][4];
    #pragma unroll
    for (int kc = 0; kc < 4; kc++)
        ldsm_x4(qf[kc], smem_u32(Qsh + (w * 16 + lr) * HP + kc * 16 + lc));
    __syncthreads();

    float oacc[8][4];
    #pragma unroll
    for (int nt = 0; nt < 8; nt++)
        #pragma unroll
        for (int e = 0; e < 4; e++) oacc[nt][e] = 0.f;

    float m_lo = -INFINITY, m_hi = -INFINITY, l_lo = 0.f, l_hi = 0.f;
    const float scale2 = 0.125f * 1.44269504089f;   // (1/sqrt(64)) * log2(e)

    auto load_kv = [&](int kt, int st) {
        const __half* kb = qkv + ((size_t)(b * SEQ + kt * 64)) * QKVN + h * HDIM + EMB;
        const __half* vb = kb + EMB;
        __half* ks = Ksh + st * TILE_H;
        __half* vs = Vsh + st * TILE_H;
        for (int i = tid; i < 64 * 8; i += 128) {
            int r = i >> 3, c = i & 7;
            cp16(ks + r * HP + c * 8, kb + (size_t)r * QKVN + c * 8);
            cp16(vs + r * HP + c * 8, vb + (size_t)r * QKVN + c * 8);
        }
        asm volatile("cp.async.commit_group;" ::: "memory");
    };

    load_kv(0, 0);

    __half* Pw = Qsh + (w * 16) * HP;

    for (int kt = 0; kt <= qb; kt++) {
        int st = kt & 1;
        if (kt < qb) {
            load_kv(kt + 1, st ^ 1);
            asm volatile("cp.async.wait_group 1;" ::: "memory");
        } else {
            asm volatile("cp.async.wait_group 0;" ::: "memory");
        }
        __syncthreads();

        const __half* ks = Ksh + st * TILE_H;
        const __half* vs = Vsh + st * TILE_H;

        float sacc[8][4];
        #pragma unroll
        for (int nt = 0; nt < 8; nt++)
            #pragma unroll
            for (int e = 0; e < 4; e++) sacc[nt][e] = 0.f;
        #pragma unroll
        for (int kc = 0; kc < 4; kc++) {
            #pragma unroll
            for (int nb = 0; nb < 4; nb++) {
                uint32_t kf[4];
                ldsm_x4(kf, smem_u32(ks + (nb * 16 + (bseg >> 1) * 8 + br) * HP
                                        + kc * 16 + (bseg & 1) * 8));
                mma16(sacc[nb * 2],     qf[kc], kf);
                mma16(sacc[nb * 2 + 1], qf[kc], kf + 2);
            }
        }

        // scores in log2 domain
        float tl = -INFINITY, th = -INFINITY;
        const int row_lo = w * 16 + g;
        const int row_hi = row_lo + 8;
        #pragma unroll
        for (int nt = 0; nt < 8; nt++) {
            float s0 = sacc[nt][0] * scale2;
            float s1 = sacc[nt][1] * scale2;
            float s2 = sacc[nt][2] * scale2;
            float s3 = sacc[nt][3] * scale2;
            if (kt == qb) {
                int c0 = nt * 8 + t * 2, c1 = c0 + 1;
                if (c0 > row_lo) s0 = -INFINITY;
                if (c1 > row_lo) s1 = -INFINITY;
                if (c0 > row_hi) s2 = -INFINITY;
                if (c1 > row_hi) s3 = -INFINITY;
            }
            sacc[nt][0] = s0; sacc[nt][1] = s1; sacc[nt][2] = s2; sacc[nt][3] = s3;
            tl = fmaxf(tl, fmaxf(s0, s1));
            th = fmaxf(th, fmaxf(s2, s3));
        }
        tl = fmaxf(tl, __shfl_xor_sync(0xffffffffu, tl, 1));
        tl = fmaxf(tl, __shfl_xor_sync(0xffffffffu, tl, 2));
        th = fmaxf(th, __shfl_xor_sync(0xffffffffu, th, 1));
        th = fmaxf(th, __shfl_xor_sync(0xffffffffu, th, 2));

        float mn_lo = fmaxf(m_lo, tl);
        float mn_hi = fmaxf(m_hi, th);
        float c_lo = ex2(m_lo - mn_lo);
        float c_hi = ex2(m_hi - mn_hi);

        float sl = 0.f, sh2 = 0.f;
        #pragma unroll
        for (int nt = 0; nt < 8; nt++) {
            float p0 = ex2(sacc[nt][0] - mn_lo);
            float p1 = ex2(sacc[nt][1] - mn_lo);
            float p2 = ex2(sacc[nt][2] - mn_hi);
            float p3 = ex2(sacc[nt][3] - mn_hi);
            sl += p0 + p1; sh2 += p2 + p3;
            int c = nt * 8 + t * 2;
            *(half2*)&Pw[g * HP + c]       = __floats2half2_rn(p0, p1);
            *(half2*)&Pw[(g + 8) * HP + c] = __floats2half2_rn(p2, p3);
        }
        sl  += __shfl_xor_sync(0xffffffffu, sl, 1);
        sl  += __shfl_xor_sync(0xffffffffu, sl, 2);
        sh2 += __shfl_xor_sync(0xffffffffu, sh2, 1);
        sh2 += __shfl_xor_sync(0xffffffffu, sh2, 2);
        l_lo = l_lo * c_lo + sl;
        l_hi = l_hi * c_hi + sh2;
        m_lo = mn_lo; m_hi = mn_hi;

        #pragma unroll
        for (int nt = 0; nt < 8; nt++) {
            oacc[nt][0] *= c_lo; oacc[nt][1] *= c_lo;
            oacc[nt][2] *= c_hi; oacc[nt][3] *= c_hi;
        }
        __syncwarp();

        #pragma unroll
        for (int kc = 0; kc < 4; kc++) {
            uint32_t pf[4];
            ldsm_x4(pf, smem_u32(Pw + lr * HP + kc * 16 + lc));
            #pragma unroll
            for (int nb = 0; nb < 4; nb++) {
                uint32_t vf[4];
                ldsm_x4t(vf, smem_u32(vs + (kc * 16 + (bseg & 1) * 8 + br) * HP
                                         + nb * 16 + (bseg >> 1) * 8));
                mma16(oacc[nb * 2],     pf, vf);
                mma16(oacc[nb * 2 + 1], pf, vf + 2);
            }
        }
        __syncthreads();
    }

    // fast reciprocal (MUFU.RCP) — full-precision div is a multi-instr slow path
    float inv_lo = __fdividef(1.f, l_lo);
    float inv_hi = __fdividef(1.f, l_hi);
    __half* ob = ctx + ((size_t)(b * SEQ + qb * 64 + w * 16)) * EMB + h * HDIM;
    #pragma unroll
    for (int nt = 0; nt < 8; nt++) {
        int c = nt * 8 + t * 2;
        *(half2*)(ob + (size_t)g * EMB + c) =
            __floats2half2_rn(oacc[nt][0] * inv_lo, oacc[nt][1] * inv_lo);
        *(half2*)(ob + (size_t)(g + 8) * EMB + c) =
            __floats2half2_rn(oacc[nt][2] * inv_hi, oacc[nt][3] * inv_hi);
    }
}

// ----------------------------------------------------------------------------
// Launch — weight prep on side stream via legal capture fork (evRoot)
// ----------------------------------------------------------------------------
extern "C" void kernel_launch(void* const* d_in, const int* in_sizes, int n_in,
                              void* d_out, int out_size)
{
    const float* x    = (const float*)d_in[0];
    const float* Wq   = (const float*)d_in[1];
    const float* Wk   = (const float*)d_in[2];
    const float* Wv   = (const float*)d_in[3];
    const float* Wo   = (const float*)d_in[4];
    const float* bo   = (const float*)d_in[5];
    const float* W1   = (const float*)d_in[6];
    const float* b1   = (const float*)d_in[7];
    const float* W2   = (const float*)d_in[8];
    const float* b2   = (const float*)d_in[9];
    const float* ln1s = (const float*)d_in[10];
    const float* ln1b = (const float*)d_in[11];
    const float* ln2s = (const float*)d_in[12];
    const float* ln2b = (const float*)d_in[13];
    float* out = (float*)d_out;

    __half *h_p, *qkv_p, *ctx_p, *ff_p, *wqkv_p, *wo_p, *w1_p, *w2_p;
    float *x1_p;
    cudaGetSymbolAddress((void**)&h_p,    g_h);
    cudaGetSymbolAddress((void**)&qkv_p,  g_qkv);
    cudaGetSymbolAddress((void**)&ctx_p,  g_ctx);
    cudaGetSymbolAddress((void**)&x1_p,   g_x1);
    cudaGetSymbolAddress((void**)&ff_p,   g_ff);
    cudaGetSymbolAddress((void**)&wqkv_p, g_wqkv);
    cudaGetSymbolAddress((void**)&wo_p,   g_wo);
    cudaGetSymbolAddress((void**)&w1_p,   g_w1);
    cudaGetSymbolAddress((void**)&w2_p,   g_w2);

    cudaFuncSetAttribute(gemm_mma, cudaFuncAttributeMaxDynamicSharedMemorySize, GEMM_SMEM);
    cudaFuncSetAttribute(attn_mma, cudaFuncAttributeMaxDynamicSharedMemorySize, ATTN_SMEM);

    cudaStream_t s2;
    cudaStreamCreateWithFlags(&s2, cudaStreamNonBlocking);
    cudaEvent_t evRoot, evQKVw, evW;
    cudaEventCreateWithFlags(&evRoot, cudaEventDisableTiming);
    cudaEventCreateWithFlags(&evQKVw, cudaEventDisableTiming);
    cudaEventCreateWithFlags(&evW,    cudaEventDisableTiming);

    // legal capture fork: record on origin stream, side stream waits on it
    cudaEventRecord(evRoot, 0);
    cudaStreamWaitEvent(s2, evRoot, 0);

    // side stream: weight prep
    pack_qkv_h<<<(EMB * EMB / 8 + 255) / 256, 256, 0, s2>>>(Wq, Wk, Wv, wqkv_p);
    cudaEventRecord(evQKVw, s2);
    tohalf<<<(EMB * EMB / 8 + 255) / 256, 256, 0, s2>>>(Wo, wo_p, EMB * EMB);
    tohalf<<<(EMB * FFDIM / 8 + 255) / 256, 256, 0, s2>>>(W1, w1_p, EMB * FFDIM);
    tohalf<<<(EMB * FFDIM / 8 + 255) / 256, 256, 0, s2>>>(W2, w2_p, FFDIM * EMB);
    cudaEventRecord(evW, s2);

    // main stream
    ln_kernel<<<MROWS, 256>>>(x, ln1s, ln1b, h_p);

    dim3 gqkv(QKVN / 128, MROWS / BM);
    dim3 g1024(EMB / 128, MROWS / BM);
    dim3 g4096(FFDIM / 128, MROWS / BM);

    cudaStreamWaitEvent(0, evQKVw, 0);
    gemm_mma<<<gqkv, 512, GEMM_SMEM>>>(h_p, wqkv_p, nullptr, nullptr, qkv_p,
                                       QKVN, EMB, 2);

    dim3 attn_grid(BATCH * HEADS, SEQ / 64);
    attn_mma<<<attn_grid, 128, ATTN_SMEM>>>(qkv_p, ctx_p);

    cudaStreamWaitEvent(0, evW, 0);
    gemm_mma<<<g1024, 512, GEMM_SMEM>>>(ctx_p, wo_p, bo, x, x1_p, EMB, EMB, 0);

    ln_kernel<<<MROWS, 256>>>(x1_p, ln2s, ln2b, h_p);

    gemm_mma<<<g4096, 512, GEMM_SMEM>>>(h_p, w1_p, b1, nullptr, ff_p, FFDIM, EMB, 3);

    gemm_mma<<<g1024, 512, GEMM_SMEM>>>(ff_p, w2_p, b2, x1_p, out, EMB, FFDIM, 0);
}